// round 11
// baseline (speedup 1.0000x reference)
#include <cuda_runtime.h>
#include <cuda_bf16.h>
#include <math.h>
#include <stdint.h>

// Problem constants
#define Bb   4
#define Tt   1024
#define Dd   1024
#define Hh   16
#define HD   64
#define DFF  4096
#define NT   (Bb*Tt)          // 4096 rows
#define D3   (3*Dd)           // 3072
#define DFF2 (2*DFF)          // 8192
#define BH   (Bb*Hh)          // 64

typedef __nv_bfloat16 bf16;

// ---------------- scratch (device globals; no allocation allowed) ----------
__device__ float g_qkv [NT*D3];        // QKV GEMM output
__device__ float g_attn[NT*Dd];        // attention out, [B,T,D]
__device__ float g_x   [NT*Dd];        // x_value + attn (residual stream)

// attention bf16 hi/lo operands (head-major [bh][t][d]; vt is [bh][d][t])
__device__ bf16 g_qhi[NT*Dd], g_qlo[NT*Dd];
__device__ bf16 g_khi[NT*Dd], g_klo[NT*Dd];
__device__ bf16 g_vthi[NT*Dd], g_vtlo[NT*Dd];

// hi/lo bf16 split activations
__device__ bf16 g_h_hi [NT*Dd],  g_h_lo [NT*Dd];    // LN1 out
__device__ bf16 g_h2_hi[NT*Dd],  g_h2_lo[NT*Dd];    // LN2 out
__device__ bf16 g_g_hi [NT*DFF], g_g_lo [NT*DFF];   // swiglu out (fused in fc1)
// hi/lo bf16 split weights, TRANSPOSED to [N][K] (fc1 rows interleaved a/gate)
__device__ bf16 g_wqkv_hi[D3*Dd],  g_wqkv_lo[D3*Dd];
__device__ bf16 g_w1_hi [DFF2*Dd], g_w1_lo [DFF2*Dd];
__device__ bf16 g_w2_hi [Dd*DFF],  g_w2_lo [Dd*DFF];

__device__ __forceinline__ void split_bf(float v, bf16& hi, bf16& lo) {
    hi = __float2bfloat16(v);
    lo = __float2bfloat16(v - __bfloat162float(hi));
}
__device__ __forceinline__ unsigned pack_bf2(float x, float y) {
    __nv_bfloat162 t = __floats2bfloat162_rn(x, y);
    return *(unsigned*)&t;
}
__device__ __forceinline__ uint32_t smem_u32(const void* p) {
    uint32_t a;
    asm("{ .reg .u64 t; cvta.to.shared.u64 t, %1; cvt.u32.u64 %0, t; }" : "=r"(a) : "l"(p));
    return a;
}

// ---------------- block reduce ----------------
__device__ __forceinline__ float block_reduce_sum_256(float val) {
    __shared__ float sh[32];
    int lane = threadIdx.x & 31, wid = threadIdx.x >> 5;
    #pragma unroll
    for (int o = 16; o; o >>= 1) val += __shfl_down_sync(0xffffffffu, val, o);
    if (lane == 0) sh[wid] = val;
    __syncthreads();
    if (wid == 0) {
        float v = (lane < 8) ? sh[lane] : 0.0f;
        #pragma unroll
        for (int o = 4; o; o >>= 1) v += __shfl_down_sync(0xffffffffu, v, o);
        if (lane == 0) sh[0] = v;
    }
    __syncthreads();
    float out = sh[0];
    __syncthreads();
    return out;
}

// ---------------- LayerNorm -> bf16 hi/lo (optional residual + xsave) ------
__global__ void ln_kernel(const float* __restrict__ x, const float* __restrict__ res,
                          const float* __restrict__ w, const float* __restrict__ b,
                          float* __restrict__ xsave,
                          bf16* __restrict__ yhi, bf16* __restrict__ ylo) {
    int row = blockIdx.x;
    const float* xp = x + (size_t)row * Dd;
    float v[4];
    float s = 0.0f;
    #pragma unroll
    for (int i = 0; i < 4; i++) {
        int c = threadIdx.x + i * 256;
        float t = xp[c];
        if (res) t += res[(size_t)row * Dd + c];
        v[i] = t;
        s += t;
    }
    if (xsave) {
        #pragma unroll
        for (int i = 0; i < 4; i++) xsave[(size_t)row * Dd + threadIdx.x + i * 256] = v[i];
    }
    float mean = block_reduce_sum_256(s) * (1.0f / Dd);
    float sq = 0.0f;
    #pragma unroll
    for (int i = 0; i < 4; i++) { float d = v[i] - mean; sq += d * d; }
    float var = block_reduce_sum_256(sq) * (1.0f / Dd);
    float inv = rsqrtf(var + 1e-5f);
    #pragma unroll
    for (int i = 0; i < 4; i++) {
        int c = threadIdx.x + i * 256;
        float yv = (v[i] - mean) * inv * w[c] + b[c];
        bf16 hi, lo; split_bf(yv, hi, lo);
        size_t off = (size_t)row * Dd + c;
        yhi[off] = hi; ylo[off] = lo;
    }
}

// ---------------- weight convert + transpose: W[K][N] -> Whi/lo [N][K] -----
// ilv=1 (fc1): logical N row n -> physical row 2n (a) / 2(n-DFF)+1 (gate).
__global__ void conv_w_kernel(const float* __restrict__ W,
                              bf16* __restrict__ Whi, bf16* __restrict__ Wlo,
                              int K, int N, int ilv) {
    __shared__ float tile[32][33];
    int nb = blockIdx.x * 32, kb = blockIdx.y * 32;
    int tx = threadIdx.x, ty = threadIdx.y;
    #pragma unroll
    for (int i = 0; i < 4; i++)
        tile[ty + i * 8][tx] = W[(size_t)(kb + ty + i * 8) * N + nb + tx];
    __syncthreads();
    #pragma unroll
    for (int i = 0; i < 4; i++) {
        float v = tile[tx][ty + i * 8];
        int nlog = nb + ty + i * 8;
        int nr = ilv ? (nlog < DFF ? 2 * nlog : 2 * (nlog - DFF) + 1) : nlog;
        size_t o = (size_t)nr * K + kb + tx;
        bf16 hi, lo; split_bf(v, hi, lo);
        Whi[o] = hi; Wlo[o] = lo;
    }
}

// ---------------- v transpose + split: qkv v-part -> vt hi/lo [bh][d][t] ---
__global__ void vtrans_kernel(const float* __restrict__ qkv,
                              bf16* __restrict__ vthi, bf16* __restrict__ vtlo) {
    __shared__ float tile[32][33];
    int bh = blockIdx.z;
    int b = bh >> 4, h = bh & 15;
    int tb = blockIdx.x * 32, db = blockIdx.y * 32;
    int tx = threadIdx.x, ty = threadIdx.y;
    #pragma unroll
    for (int i = 0; i < 4; i++)
        tile[ty + i * 8][tx] =
            qkv[((size_t)(b * Tt + tb + ty + i * 8)) * D3 + 2 * Dd + h * HD + db + tx];
    __syncthreads();
    #pragma unroll
    for (int i = 0; i < 4; i++) {
        float val = tile[tx][ty + i * 8];
        size_t o = ((size_t)bh * HD + db + ty + i * 8) * Tt + tb + tx;
        bf16 hi, lo; split_bf(val, hi, lo);
        vthi[o] = hi; vtlo[o] = lo;
    }
}

// ---------------- mma helpers ------------------------------------------------
__device__ __forceinline__ void cp16(unsigned saddr, const void* g) {
    asm volatile("cp.async.cg.shared.global [%0], [%1], 16;\n" :: "r"(saddr), "l"(g));
}
__device__ __forceinline__ unsigned ld_u32(const bf16* p) {
    return *(const unsigned*)p;
}
__device__ __forceinline__ void mma_bf16(float d[4], unsigned a0, unsigned a1,
                                         unsigned a2, unsigned a3,
                                         unsigned b0, unsigned b1) {
    asm volatile(
        "mma.sync.aligned.m16n8k16.row.col.f32.bf16.bf16.f32 "
        "{%0,%1,%2,%3}, {%4,%5,%6,%7}, {%8,%9}, {%0,%1,%2,%3};\n"
        : "+f"(d[0]), "+f"(d[1]), "+f"(d[2]), "+f"(d[3])
        : "r"(a0), "r"(a1), "r"(a2), "r"(a3), "r"(b0), "r"(b1));
}
__device__ __forceinline__ void ldsm_x4(unsigned& r0, unsigned& r1,
                                        unsigned& r2, unsigned& r3, uint32_t a) {
    asm volatile("ldmatrix.sync.aligned.m8n8.x4.shared.b16 {%0,%1,%2,%3}, [%4];"
                 : "=r"(r0), "=r"(r1), "=r"(r2), "=r"(r3) : "r"(a));
}

// ---------------- tensor-core GEMM with bf16 hi/lo 3-pass ------------------
// C[M,N] = A[M,K] @ B[K,N]; A hi/lo [M][K], B hi/lo TRANSPOSED [N][K].
// BM=128, BN=256, BK=32, 256 threads (8 warps, 64x64 per warp), double buffer.
// Stage layout (halves, stride ASTR): Ahi rows 0-127 @0, Alo @5120,
//   Bhi 256 rows @10240, Blo @20480. STAGE = 768*ASTR halves.
// mode 0: C = result. mode 1 (fc1): interleaved a/gate cols -> swiglu -> Ghi/Glo.
// mode 2 (fc2): C = result + xres + bias.
#define ASTR 40
#define STAGE_HALVES (768*ASTR)         // 30720 halves = 61440 B per stage

__global__ __launch_bounds__(256) void gemm_mma_kernel(
    const bf16* __restrict__ Ahi, const bf16* __restrict__ Alo,
    const bf16* __restrict__ Bhi, const bf16* __restrict__ Blo,
    float* __restrict__ C, bf16* __restrict__ Ghi, bf16* __restrict__ Glo,
    const float* __restrict__ bias, const float* __restrict__ xres,
    int M, int N, int K, int mode) {
    extern __shared__ bf16 smem[];
    const int tid  = threadIdx.x;
    const int lane = tid & 31, wid = tid >> 5;
    const int bm = blockIdx.y, bn = blockIdx.x;
    const int warp_m = (wid & 1) * 64;
    const int warp_n = (wid >> 1) * 64;

    // ldmatrix lane-address components
    const int lq = lane & 7, lg = lane >> 3;
    const int aro = lq + (lg & 1) * 8;
    const int aco = (lg >> 1) * 8;
    const int bro = lq + (lg >> 1) * 8;
    const int bco = (lg & 1) * 8;

    const int r  = tid >> 2;              // 0..63
    const int kc = (tid & 3) * 8;
    const bf16* gAhi = Ahi + (size_t)(bm * 128 + r) * K + kc;
    const bf16* gAlo = Alo + (size_t)(bm * 128 + r) * K + kc;
    const bf16* gBhi = Bhi + (size_t)(bn * 256 + r) * K + kc;
    const bf16* gBlo = Blo + (size_t)(bn * 256 + r) * K + kc;
    const size_t ro64 = (size_t)64 * K;

    unsigned sbase = smem_u32(smem);
    unsigned sRow = sbase + (r * ASTR + kc) * 2;   // row r within a section

    float d[4][8][4];
    #pragma unroll
    for (int i = 0; i < 4; i++)
        #pragma unroll
        for (int j = 0; j < 8; j++)
            #pragma unroll
            for (int e = 0; e < 4; e++) d[i][j][e] = 0.0f;

    const int ntiles = K / 32;

#define GLOAD(koff, so) do {                                                  \
    cp16(sRow + (so),                         gAhi + (koff));                 \
    cp16(sRow + (so) + 64 * ASTR * 2,         gAhi + (koff) + ro64);          \
    cp16(sRow + (so) + 5120 * 2,              gAlo + (koff));                 \
    cp16(sRow + (so) + 5120 * 2 + 64 * ASTR * 2, gAlo + (koff) + ro64);       \
    _Pragma("unroll")                                                         \
    for (int q = 0; q < 4; q++) {                                             \
        cp16(sRow + (so) + (10240 + q * 64 * ASTR) * 2, gBhi + (koff) + q * ro64); \
        cp16(sRow + (so) + (20480 + q * 64 * ASTR) * 2, gBlo + (koff) + q * ro64); \
    }                                                                         \
    asm volatile("cp.async.commit_group;\n");                                 \
} while (0)

    GLOAD(0, 0);

    for (int kt = 0; kt < ntiles; kt++) {
        if (kt + 1 < ntiles) {
            GLOAD((kt + 1) * 32, ((kt + 1) & 1) * (STAGE_HALVES * 2));
            asm volatile("cp.async.wait_group 1;\n");
        } else {
            asm volatile("cp.async.wait_group 0;\n");
        }
        __syncthreads();

        const unsigned stb = sbase + (kt & 1) * (STAGE_HALVES * 2);
        #pragma unroll
        for (int ks = 0; ks < 2; ks++) {
            unsigned ahi[4][4], alo[4][4], bhi[8][2], blo[8][2];
            #pragma unroll
            for (int mt = 0; mt < 4; mt++) {
                unsigned ad = stb + ((warp_m + mt * 16 + aro) * ASTR + ks * 16 + aco) * 2;
                ldsm_x4(ahi[mt][0], ahi[mt][1], ahi[mt][2], ahi[mt][3], ad);
                ldsm_x4(alo[mt][0], alo[mt][1], alo[mt][2], alo[mt][3], ad + 5120 * 2);
            }
            #pragma unroll
            for (int np = 0; np < 4; np++) {
                unsigned bd = stb + 10240 * 2 +
                              ((warp_n + np * 16 + bro) * ASTR + ks * 16 + bco) * 2;
                ldsm_x4(bhi[2 * np][0], bhi[2 * np][1],
                        bhi[2 * np + 1][0], bhi[2 * np + 1][1], bd);
                ldsm_x4(blo[2 * np][0], blo[2 * np][1],
                        blo[2 * np + 1][0], blo[2 * np + 1][1], bd + 10240 * 2);
            }
            #pragma unroll
            for (int mt = 0; mt < 4; mt++)
                #pragma unroll
                for (int nt = 0; nt < 8; nt++) {
                    mma_bf16(d[mt][nt], ahi[mt][0], ahi[mt][1], ahi[mt][2], ahi[mt][3],
                             bhi[nt][0], bhi[nt][1]);
                    mma_bf16(d[mt][nt], ahi[mt][0], ahi[mt][1], ahi[mt][2], ahi[mt][3],
                             blo[nt][0], blo[nt][1]);
                    mma_bf16(d[mt][nt], alo[mt][0], alo[mt][1], alo[mt][2], alo[mt][3],
                             bhi[nt][0], bhi[nt][1]);
                }
        }
        __syncthreads();
    }

    // epilogue (modes)
    #pragma unroll
    for (int mt = 0; mt < 4; mt++) {
        int row = bm * 128 + warp_m + mt * 16 + (lane >> 2);
        #pragma unroll
        for (int nt = 0; nt < 8; nt++) {
            int col = bn * 256 + warp_n + nt * 8 + (lane & 3) * 2;
            if (mode == 0) {
                *(float2*)(C + (size_t)row * N + col) =
                    make_float2(d[mt][nt][0], d[mt][nt][1]);
                *(float2*)(C + (size_t)(row + 8) * N + col) =
                    make_float2(d[mt][nt][2], d[mt][nt][3]);
            } else if (mode == 2) {
                {
                    size_t o = (size_t)row * N + col;
                    *(float2*)(C + o) = make_float2(
                        d[mt][nt][0] + xres[o] + bias[col],
                        d[mt][nt][1] + xres[o + 1] + bias[col + 1]);
                }
                {
                    size_t o = (size_t)(row + 8) * N + col;
                    *(float2*)(C + o) = make_float2(
                        d[mt][nt][2] + xres[o] + bias[col],
                        d[mt][nt][3] + xres[o + 1] + bias[col + 1]);
                }
            } else {
                // swiglu: pair (col, col+1) = (a_n, gate_n), n = col/2
                int n = col >> 1;
                float ba = bias[n], bg = bias[DFF + n];
                float a0 = d[mt][nt][0] + ba, g0 = d[mt][nt][1] + bg;
                float a1 = d[mt][nt][2] + ba, g1 = d[mt][nt][3] + bg;
                float v0 = g0 * (1.0f / (1.0f + __expf(-g0))) * a0;
                float v1 = g1 * (1.0f / (1.0f + __expf(-g1))) * a1;
                bf16 hi, lo;
                split_bf(v0, hi, lo);
                Ghi[(size_t)row * DFF + n] = hi;       Glo[(size_t)row * DFF + n] = lo;
                split_bf(v1, hi, lo);
                Ghi[(size_t)(row + 8) * DFF + n] = hi; Glo[(size_t)(row + 8) * DFF + n] = lo;
            }
        }
    }
#undef GLOAD
}

// ---------------- type-emb add + RoPE + head transpose -> bf16 hi/lo -------
// q scaled by 1/sqrt(HD) here. v handled by vtrans straight from qkv.
__global__ void rope_kernel(const float* __restrict__ qkv, const int* __restrict__ x_type,
                            const int* __restrict__ seq_order,
                            const float* __restrict__ type_emb,
                            bf16* __restrict__ qhi, bf16* __restrict__ qlo,
                            bf16* __restrict__ khi, bf16* __restrict__ klo) {
    int idx = blockIdx.x * 256 + threadIdx.x;
    int i = idx & 31;
    int t = (idx >> 5) & (Tt - 1);
    int h = (idx >> 15) & (Hh - 1);
    int b = idx >> 19;
    int row = b * Tt + t;
    int bh = b * Hh + h;
    int ty = x_type[row];

    const float* qrow = qkv + (size_t)row * D3;
    const float* te = type_emb + (size_t)ty * (2 * Dd);
    int cb = h * HD + 2 * i;

    float q0 = qrow[cb]           + te[cb];
    float q1 = qrow[cb + 1]       + te[cb + 1];
    float k0 = qrow[Dd + cb]      + te[Dd + cb];
    float k1 = qrow[Dd + cb + 1]  + te[Dd + cb + 1];

    if (i < 16) {
        float pos = (float)seq_order[row];
        float invf = __powf(10000.0f, -(float)i * (1.0f / 16.0f));
        float ang = pos * invf;
        float c, s;
        sincosf(ang, &s, &c);
        float rq0 = q0 * c - q1 * s;
        float rq1 = q1 * c + q0 * s;
        float rk0 = k0 * c - k1 * s;
        float rk1 = k1 * c + k0 * s;
        q0 = rq0; q1 = rq1; k0 = rk0; k1 = rk1;
    }
    q0 *= 0.125f; q1 *= 0.125f;
    size_t o = ((size_t)bh * Tt + t) * HD + 2 * i;
    bf16 hi, lo;
    split_bf(q0, hi, lo); qhi[o] = hi;     qlo[o] = lo;
    split_bf(q1, hi, lo); qhi[o + 1] = hi; qlo[o + 1] = lo;
    split_bf(k0, hi, lo); khi[o] = hi;     klo[o] = lo;
    split_bf(k1, hi, lo); khi[o + 1] = hi; klo[o + 1] = lo;
}

// ---------------- tensor-core flash attention ------------------------------
// grid (T/128, BH), 256 threads (8 warps x 16 q-rows). 64-key tiles.
#define KSTR 72

__global__ __launch_bounds__(256) void attn_mma_kernel(
    const bf16* __restrict__ qhi, const bf16* __restrict__ qlo,
    const bf16* __restrict__ khi, const bf16* __restrict__ klo,
    const bf16* __restrict__ vthi, const bf16* __restrict__ vtlo,
    float* __restrict__ out) {
    __shared__ bf16 skh[64 * KSTR], skl[64 * KSTR], svh[64 * KSTR], svl[64 * KSTR];
    const int bh = blockIdx.y, qt = blockIdx.x;
    const int tid = threadIdx.x, lane = tid & 31, w = tid >> 5;
    const int g = lane >> 2, c = lane & 3;

    const int lq = lane & 7, lg = lane >> 3;
    const int bro = lq + (lg >> 1) * 8;
    const int bco = (lg & 1) * 8;
    const unsigned skh_b = smem_u32(skh), skl_b = smem_u32(skl);
    const unsigned svh_b = smem_u32(svh), svl_b = smem_u32(svl);

    const int qrow0 = qt * 128 + w * 16 + g;
    unsigned qh[4][4], ql[4][4];
    {
        const size_t base0 = ((size_t)bh * Tt + qrow0) * HD;
        const size_t base8 = base0 + 8 * HD;
        #pragma unroll
        for (int kk = 0; kk < 4; kk++) {
            int col = kk * 16 + 2 * c;
            qh[kk][0] = ld_u32(qhi + base0 + col);
            qh[kk][1] = ld_u32(qhi + base8 + col);
            qh[kk][2] = ld_u32(qhi + base0 + col + 8);
            qh[kk][3] = ld_u32(qhi + base8 + col + 8);
            ql[kk][0] = ld_u32(qlo + base0 + col);
            ql[kk][1] = ld_u32(qlo + base8 + col);
            ql[kk][2] = ld_u32(qlo + base0 + col + 8);
            ql[kk][3] = ld_u32(qlo + base8 + col + 8);
        }
    }

    float O[8][4];
    #pragma unroll
    for (int i = 0; i < 8; i++)
        #pragma unroll
        for (int j = 0; j < 4; j++) O[i][j] = 0.0f;
    float m0 = -1e30f, m1 = -1e30f, l0 = 0.0f, l1 = 0.0f;

    for (int kt = 0; kt < Tt / 64; kt++) {
        __syncthreads();
        {
            const size_t kg = ((size_t)bh * Tt + kt * 64) * HD;
            #pragma unroll
            for (int it = 0; it < 2; it++) {
                int idx = it * 256 + tid;
                int rr = idx >> 3, cc = (idx & 7) * 8;
                *(float4*)&skh[rr * KSTR + cc] = *(const float4*)(khi + kg + rr * HD + cc);
                *(float4*)&skl[rr * KSTR + cc] = *(const float4*)(klo + kg + rr * HD + cc);
                size_t vg = ((size_t)bh * HD + rr) * Tt + kt * 64 + cc;
                *(float4*)&svh[rr * KSTR + cc] = *(const float4*)(vthi + vg);
                *(float4*)&svl[rr * KSTR + cc] = *(const float4*)(vtlo + vg);
            }
        }
        __syncthreads();

        // ---- S = Q K^T (3-pass), K frags via ldmatrix ----
        float S[8][4];
        #pragma unroll
        for (int i = 0; i < 8; i++)
            #pragma unroll
            for (int j = 0; j < 4; j++) S[i][j] = 0.0f;
        #pragma unroll
        for (int kk = 0; kk < 4; kk++) {
            #pragma unroll
            for (int np = 0; np < 4; np++) {
                unsigned off = ((np * 16 + bro) * KSTR + kk * 16 + bco) * 2;
                unsigned h0, h1, h2, h3, l0r, l1r, l2r, l3r;
                ldsm_x4(h0, h1, h2, h3, skh_b + off);
                ldsm_x4(l0r, l1r, l2r, l3r, skl_b + off);
                mma_bf16(S[2 * np],     qh[kk][0], qh[kk][1], qh[kk][2], qh[kk][3], h0, h1);
                mma_bf16(S[2 * np],     qh[kk][0], qh[kk][1], qh[kk][2], qh[kk][3], l0r, l1r);
                mma_bf16(S[2 * np],     ql[kk][0], ql[kk][1], ql[kk][2], ql[kk][3], h0, h1);
                mma_bf16(S[2 * np + 1], qh[kk][0], qh[kk][1], qh[kk][2], qh[kk][3], h2, h3);
                mma_bf16(S[2 * np + 1], qh[kk][0], qh[kk][1], qh[kk][2], qh[kk][3], l2r, l3r);
                mma_bf16(S[2 * np + 1], ql[kk][0], ql[kk][1], ql[kk][2], ql[kk][3], h2, h3);
            }
        }

        // ---- online softmax ----
        float tm0 = -1e30f, tm1 = -1e30f;
        #pragma unroll
        for (int nn = 0; nn < 8; nn++) {
            tm0 = fmaxf(tm0, fmaxf(S[nn][0], S[nn][1]));
            tm1 = fmaxf(tm1, fmaxf(S[nn][2], S[nn][3]));
        }
        tm0 = fmaxf(tm0, __shfl_xor_sync(0xffffffffu, tm0, 1));
        tm0 = fmaxf(tm0, __shfl_xor_sync(0xffffffffu, tm0, 2));
        tm1 = fmaxf(tm1, __shfl_xor_sync(0xffffffffu, tm1, 1));
        tm1 = fmaxf(tm1, __shfl_xor_sync(0xffffffffu, tm1, 2));
        float mn0 = fmaxf(m0, tm0), mn1 = fmaxf(m1, tm1);
        float cor0 = __expf(m0 - mn0), cor1 = __expf(m1 - mn1);
        m0 = mn0; m1 = mn1;

        float rs0 = 0.0f, rs1 = 0.0f;
        #pragma unroll
        for (int nn = 0; nn < 8; nn++) {
            S[nn][0] = __expf(S[nn][0] - mn0);
            S[nn][1] = __expf(S[nn][1] - mn0);
            S[nn][2] = __expf(S[nn][2] - mn1);
            S[nn][3] = __expf(S[nn][3] - mn1);
            rs0 += S[nn][0] + S[nn][1];
            rs1 += S[nn][2] + S[nn][3];
        }
        rs0 += __shfl_xor_sync(0xffffffffu, rs0, 1);
        rs0 += __shfl_xor_sync(0xffffffffu, rs0, 2);
        rs1 += __shfl_xor_sync(0xffffffffu, rs1, 1);
        rs1 += __shfl_xor_sync(0xffffffffu, rs1, 2);
        l0 = l0 * cor0 + rs0;
        l1 = l1 * cor1 + rs1;
        #pragma unroll
        for (int dd = 0; dd < 8; dd++) {
            O[dd][0] *= cor0; O[dd][1] *= cor0;
            O[dd][2] *= cor1; O[dd][3] *= cor1;
        }

        // ---- O += P V (3-pass); V via ldmatrix ----
        #pragma unroll
        for (int jj = 0; jj < 4; jj++) {
            float ph[8], pl[8];
            #pragma unroll
            for (int e = 0; e < 4; e++) {
                float v0 = S[2 * jj][e];
                float v1 = S[2 * jj + 1][e];
                float h0 = __bfloat162float(__float2bfloat16(v0));
                float h1 = __bfloat162float(__float2bfloat16(v1));
                ph[e]     = h0; ph[4 + e] = h1;
                pl[e]     = v0 - h0; pl[4 + e] = v1 - h1;
            }
            unsigned pah0 = pack_bf2(ph[0], ph[1]);
            unsigned pah1 = pack_bf2(ph[2], ph[3]);
            unsigned pah2 = pack_bf2(ph[4], ph[5]);
            unsigned pah3 = pack_bf2(ph[6], ph[7]);
            unsigned pal0 = pack_bf2(pl[0], pl[1]);
            unsigned pal1 = pack_bf2(pl[2], pl[3]);
            unsigned pal2 = pack_bf2(pl[4], pl[5]);
            unsigned pal3 = pack_bf2(pl[6], pl[7]);
            #pragma unroll
            for (int dp = 0; dp < 4; dp++) {
                unsigned off = ((dp * 16 + bro) * KSTR + jj * 16 + bco) * 2;
                unsigned v0r, v1r, v2r, v3r, w0r, w1r, w2r, w3r;
                ldsm_x4(v0r, v1r, v2r, v3r, svh_b + off);
                ldsm_x4(w0r, w1r, w2r, w3r, svl_b + off);
                mma_bf16(O[2 * dp],     pah0, pah1, pah2, pah3, v0r, v1r);
                mma_bf16(O[2 * dp],     pah0, pah1, pah2, pah3, w0r, w1r);
                mma_bf16(O[2 * dp],     pal0, pal1, pal2, pal3, v0r, v1r);
                mma_bf16(O[2 * dp + 1], pah0, pah1, pah2, pah3, v2r, v3r);
                mma_bf16(O[2 * dp + 1], pah0, pah1, pah2, pah3, w2r, w3r);
                mma_bf16(O[2 * dp + 1], pal0, pal1, pal2, pal3, v2r, v3r);
            }
        }
    }

    float inv0 = 1.0f / l0, inv1 = 1.0f / l1;
    const int b = bh >> 4, h = bh & 15;
    const int trow = qt * 128 + w * 16 + g;
    #pragma unroll
    for (int dd = 0; dd < 8; dd++) {
        int col = h * HD + dd * 8 + 2 * c;
        *(float2*)(out + ((size_t)(b * Tt + trow)) * Dd + col) =
            make_float2(O[dd][0] * inv0, O[dd][1] * inv0);
        *(float2*)(out + ((size_t)(b * Tt + trow + 8)) * Dd + col) =
            make_float2(O[dd][2] * inv1, O[dd][3] * inv1);
    }
}

// ---------------- launch ----------------------------------------------------
extern "C" void kernel_launch(void* const* d_in, const int* in_sizes, int n_in,
                              void* d_out, int out_size) {
    const int*   x_type    = (const int*)  d_in[0];
    const float* x_value   = (const float*)d_in[1];
    const int*   seq_order = (const int*)  d_in[2];
    const float* Wqkv      = (const float*)d_in[3];
    const float* type_emb  = (const float*)d_in[4];
    const float* ln1_w     = (const float*)d_in[5];
    const float* ln1_b     = (const float*)d_in[6];
    const float* ln2_w     = (const float*)d_in[7];
    const float* ln2_b     = (const float*)d_in[8];
    const float* fc1_w     = (const float*)d_in[9];
    const float* fc1_b     = (const float*)d_in[10];
    const float* fc2_w     = (const float*)d_in[11];
    const float* fc2_b     = (const float*)d_in[12];
    float* out = (float*)d_out;

    float *qkv, *attn, *x;
    bf16 *qhi, *qlo, *khi, *klo, *vthi, *vtlo;
    bf16 *h_hi, *h_lo, *h2_hi, *h2_lo, *gg_hi, *gg_lo;
    bf16 *wqkv_hi, *wqkv_lo, *w1_hi, *w1_lo, *w2_hi, *w2_lo;
    cudaGetSymbolAddress((void**)&qkv,     g_qkv);
    cudaGetSymbolAddress((void**)&attn,    g_attn);
    cudaGetSymbolAddress((void**)&x,       g_x);
    cudaGetSymbolAddress((void**)&qhi,     g_qhi);
    cudaGetSymbolAddress((void**)&qlo,     g_qlo);
    cudaGetSymbolAddress((void**)&khi,     g_khi);
    cudaGetSymbolAddress((void**)&klo,     g_klo);
    cudaGetSymbolAddress((void**)&vthi,    g_vthi);
    cudaGetSymbolAddress((void**)&vtlo,    g_vtlo);
    cudaGetSymbolAddress((void**)&h_hi,    g_h_hi);
    cudaGetSymbolAddress((void**)&h_lo,    g_h_lo);
    cudaGetSymbolAddress((void**)&h2_hi,   g_h2_hi);
    cudaGetSymbolAddress((void**)&h2_lo,   g_h2_lo);
    cudaGetSymbolAddress((void**)&gg_hi,   g_g_hi);
    cudaGetSymbolAddress((void**)&gg_lo,   g_g_lo);
    cudaGetSymbolAddress((void**)&wqkv_hi, g_wqkv_hi);
    cudaGetSymbolAddress((void**)&wqkv_lo, g_wqkv_lo);
    cudaGetSymbolAddress((void**)&w1_hi,   g_w1_hi);
    cudaGetSymbolAddress((void**)&w1_lo,   g_w1_lo);
    cudaGetSymbolAddress((void**)&w2_hi,   g_w2_hi);
    cudaGetSymbolAddress((void**)&w2_lo,   g_w2_lo);

    cudaFuncSetAttribute(gemm_mma_kernel,
                         cudaFuncAttributeMaxDynamicSharedMemorySize, 2 * STAGE_HALVES * 2);
    const int smem_bytes = 2 * STAGE_HALVES * 2;   // 122880

    // weight conversion (+transpose to [N][K]); fc1 rows interleaved a/gate
    conv_w_kernel<<<dim3(D3 / 32, Dd / 32),   dim3(32, 8)>>>(Wqkv,  wqkv_hi, wqkv_lo, Dd, D3, 0);
    conv_w_kernel<<<dim3(DFF2 / 32, Dd / 32), dim3(32, 8)>>>(fc1_w, w1_hi,   w1_lo,   Dd, DFF2, 1);
    conv_w_kernel<<<dim3(Dd / 32, DFF / 32),  dim3(32, 8)>>>(fc2_w, w2_hi,   w2_lo,   DFF, Dd, 0);

    // 1. LN1 -> bf16 hi/lo
    ln_kernel<<<NT, 256>>>(x_value, nullptr, ln1_w, ln1_b, nullptr, h_hi, h_lo);
    // 2. QKV GEMM
    gemm_mma_kernel<<<dim3(D3 / 256, NT / 128), 256, smem_bytes>>>(
        h_hi, h_lo, wqkv_hi, wqkv_lo, qkv, nullptr, nullptr, nullptr, nullptr,
        NT, D3, Dd, 0);
    // 3. type-emb + RoPE -> q/k bf16 hi/lo
    rope_kernel<<<(Bb * Hh * Tt * 32) / 256, 256>>>(
        qkv, x_type, seq_order, type_emb, qhi, qlo, khi, klo);
    // 3b. v transpose + split straight from qkv
    vtrans_kernel<<<dim3(Tt / 32, HD / 32, BH), dim3(32, 8)>>>(qkv, vthi, vtlo);
    // 4. tensor-core flash attention
    attn_mma_kernel<<<dim3(Tt / 128, BH), 256>>>(qhi, qlo, khi, klo, vthi, vtlo, attn);
    // 5. residual + LN2 (saves x = x_value + attn)
    ln_kernel<<<NT, 256>>>(x_value, attn, ln2_w, ln2_b, x, h2_hi, h2_lo);
    // 6. fc1 GEMM + fused bias/swiglu -> g hi/lo
    gemm_mma_kernel<<<dim3(DFF2 / 256, NT / 128), 256, smem_bytes>>>(
        h2_hi, h2_lo, w1_hi, w1_lo, nullptr, gg_hi, gg_lo, fc1_b, nullptr,
        NT, DFF2, Dd, 1);
    // 7. fc2 GEMM + fused bias/residual -> out
    gemm_mma_kernel<<<dim3(Dd / 256, NT / 128), 256, smem_bytes>>>(
        gg_hi, gg_lo, w2_hi, w2_lo, out, nullptr, nullptr, fc2_b, x,
        NT, Dd, DFF, 2);
}

// round 13
// speedup vs baseline: 1.0579x; 1.0579x over previous
#include <cuda_runtime.h>
#include <cuda_bf16.h>
#include <math.h>
#include <stdint.h>

// Problem constants
#define Bb   4
#define Tt   1024
#define Dd   1024
#define Hh   16
#define HD   64
#define DFF  4096
#define NT   (Bb*Tt)          // 4096 rows
#define D3   (3*Dd)           // 3072
#define DFF2 (2*DFF)          // 8192
#define BH   (Bb*Hh)          // 64

typedef __nv_bfloat16 bf16;

// ---------------- scratch (device globals; no allocation allowed) ----------
__device__ float g_qkv [NT*D3];        // QKV GEMM output
__device__ float g_attn[NT*Dd];        // attention out, [B,T,D]
__device__ float g_x   [NT*Dd];        // x_value + attn (residual stream)

// attention bf16 hi/lo operands (head-major [bh][t][d]; vt is [bh][d][t])
__device__ bf16 g_qhi[NT*Dd], g_qlo[NT*Dd];
__device__ bf16 g_khi[NT*Dd], g_klo[NT*Dd];
__device__ bf16 g_vthi[NT*Dd], g_vtlo[NT*Dd];

// hi/lo bf16 split activations
__device__ bf16 g_h_hi [NT*Dd],  g_h_lo [NT*Dd];    // LN1 out
__device__ bf16 g_h2_hi[NT*Dd],  g_h2_lo[NT*Dd];    // LN2 out
__device__ bf16 g_g_hi [NT*DFF], g_g_lo [NT*DFF];   // swiglu out (fused in fc1)
// hi/lo bf16 split weights, TRANSPOSED to [N][K] (fc1 rows interleaved a/gate)
__device__ bf16 g_wqkv_hi[D3*Dd],  g_wqkv_lo[D3*Dd];
__device__ bf16 g_w1_hi [DFF2*Dd], g_w1_lo [DFF2*Dd];
__device__ bf16 g_w2_hi [Dd*DFF],  g_w2_lo [Dd*DFF];

__device__ __forceinline__ void split_bf(float v, bf16& hi, bf16& lo) {
    hi = __float2bfloat16(v);
    lo = __float2bfloat16(v - __bfloat162float(hi));
}
__device__ __forceinline__ unsigned pack_bf2(float x, float y) {
    __nv_bfloat162 t = __floats2bfloat162_rn(x, y);
    return *(unsigned*)&t;
}
__device__ __forceinline__ uint32_t smem_u32(const void* p) {
    uint32_t a;
    asm("{ .reg .u64 t; cvta.to.shared.u64 t, %1; cvt.u32.u64 %0, t; }" : "=r"(a) : "l"(p));
    return a;
}

// ---------------- block reduce ----------------
__device__ __forceinline__ float block_reduce_sum_256(float val) {
    __shared__ float sh[32];
    int lane = threadIdx.x & 31, wid = threadIdx.x >> 5;
    #pragma unroll
    for (int o = 16; o; o >>= 1) val += __shfl_down_sync(0xffffffffu, val, o);
    if (lane == 0) sh[wid] = val;
    __syncthreads();
    if (wid == 0) {
        float v = (lane < 8) ? sh[lane] : 0.0f;
        #pragma unroll
        for (int o = 4; o; o >>= 1) v += __shfl_down_sync(0xffffffffu, v, o);
        if (lane == 0) sh[0] = v;
    }
    __syncthreads();
    float out = sh[0];
    __syncthreads();
    return out;
}

// ---------------- LayerNorm -> bf16 hi/lo (optional residual + xsave) ------
__global__ void ln_kernel(const float* __restrict__ x, const float* __restrict__ res,
                          const float* __restrict__ w, const float* __restrict__ b,
                          float* __restrict__ xsave,
                          bf16* __restrict__ yhi, bf16* __restrict__ ylo) {
    int row = blockIdx.x;
    const float* xp = x + (size_t)row * Dd;
    float v[4];
    float s = 0.0f;
    #pragma unroll
    for (int i = 0; i < 4; i++) {
        int c = threadIdx.x + i * 256;
        float t = xp[c];
        if (res) t += res[(size_t)row * Dd + c];
        v[i] = t;
        s += t;
    }
    if (xsave) {
        #pragma unroll
        for (int i = 0; i < 4; i++) xsave[(size_t)row * Dd + threadIdx.x + i * 256] = v[i];
    }
    float mean = block_reduce_sum_256(s) * (1.0f / Dd);
    float sq = 0.0f;
    #pragma unroll
    for (int i = 0; i < 4; i++) { float d = v[i] - mean; sq += d * d; }
    float var = block_reduce_sum_256(sq) * (1.0f / Dd);
    float inv = rsqrtf(var + 1e-5f);
    #pragma unroll
    for (int i = 0; i < 4; i++) {
        int c = threadIdx.x + i * 256;
        float yv = (v[i] - mean) * inv * w[c] + b[c];
        bf16 hi, lo; split_bf(yv, hi, lo);
        size_t off = (size_t)row * Dd + c;
        yhi[off] = hi; ylo[off] = lo;
    }
}

// ---------------- weight convert + transpose: W[K][N] -> Whi/lo [N][K] -----
// ilv=1 (fc1): logical N row n -> physical row 2n (a) / 2(n-DFF)+1 (gate).
__global__ void conv_w_kernel(const float* __restrict__ W,
                              bf16* __restrict__ Whi, bf16* __restrict__ Wlo,
                              int K, int N, int ilv) {
    __shared__ float tile[32][33];
    int nb = blockIdx.x * 32, kb = blockIdx.y * 32;
    int tx = threadIdx.x, ty = threadIdx.y;
    #pragma unroll
    for (int i = 0; i < 4; i++)
        tile[ty + i * 8][tx] = W[(size_t)(kb + ty + i * 8) * N + nb + tx];
    __syncthreads();
    #pragma unroll
    for (int i = 0; i < 4; i++) {
        float v = tile[tx][ty + i * 8];
        int nlog = nb + ty + i * 8;
        int nr = ilv ? (nlog < DFF ? 2 * nlog : 2 * (nlog - DFF) + 1) : nlog;
        size_t o = (size_t)nr * K + kb + tx;
        bf16 hi, lo; split_bf(v, hi, lo);
        Whi[o] = hi; Wlo[o] = lo;
    }
}

// ---------------- v transpose + split: qkv v-part -> vt hi/lo [bh][d][t] ---
__global__ void vtrans_kernel(const float* __restrict__ qkv,
                              bf16* __restrict__ vthi, bf16* __restrict__ vtlo) {
    __shared__ float tile[32][33];
    int bh = blockIdx.z;
    int b = bh >> 4, h = bh & 15;
    int tb = blockIdx.x * 32, db = blockIdx.y * 32;
    int tx = threadIdx.x, ty = threadIdx.y;
    #pragma unroll
    for (int i = 0; i < 4; i++)
        tile[ty + i * 8][tx] =
            qkv[((size_t)(b * Tt + tb + ty + i * 8)) * D3 + 2 * Dd + h * HD + db + tx];
    __syncthreads();
    #pragma unroll
    for (int i = 0; i < 4; i++) {
        float val = tile[tx][ty + i * 8];
        size_t o = ((size_t)bh * HD + db + ty + i * 8) * Tt + tb + tx;
        bf16 hi, lo; split_bf(val, hi, lo);
        vthi[o] = hi; vtlo[o] = lo;
    }
}

// ---------------- mma helpers ------------------------------------------------
__device__ __forceinline__ void cp16(unsigned saddr, const void* g) {
    asm volatile("cp.async.cg.shared.global [%0], [%1], 16;\n" :: "r"(saddr), "l"(g));
}
__device__ __forceinline__ unsigned ld_u32(const bf16* p) {
    return *(const unsigned*)p;
}
__device__ __forceinline__ void mma_bf16(float d[4], unsigned a0, unsigned a1,
                                         unsigned a2, unsigned a3,
                                         unsigned b0, unsigned b1) {
    asm volatile(
        "mma.sync.aligned.m16n8k16.row.col.f32.bf16.bf16.f32 "
        "{%0,%1,%2,%3}, {%4,%5,%6,%7}, {%8,%9}, {%0,%1,%2,%3};\n"
        : "+f"(d[0]), "+f"(d[1]), "+f"(d[2]), "+f"(d[3])
        : "r"(a0), "r"(a1), "r"(a2), "r"(a3), "r"(b0), "r"(b1));
}
__device__ __forceinline__ void ldsm_x4(unsigned& r0, unsigned& r1,
                                        unsigned& r2, unsigned& r3, uint32_t a) {
    asm volatile("ldmatrix.sync.aligned.m8n8.x4.shared.b16 {%0,%1,%2,%3}, [%4];"
                 : "=r"(r0), "=r"(r1), "=r"(r2), "=r"(r3) : "r"(a));
}

// ---------------- tensor-core GEMM with bf16 hi/lo 3-pass ------------------
// C[M,N] = A[M,K] @ B[K,N]; A hi/lo [M][K], B hi/lo TRANSPOSED [N][K].
// BM=BN=128, BK=32, 256 threads (8 warps, 64x32 per warp), double buffer.
// mode 0: C = result. mode 1 (fc1): interleaved a/gate cols -> swiglu -> Ghi/Glo.
// mode 2 (fc2): C = result + xres + bias.
#define ASTR 40                         // padded smem stride in halves
#define STAGE_HALVES (4*128*ASTR)       // per stage

__global__ __launch_bounds__(256) void gemm_mma_kernel(
    const bf16* __restrict__ Ahi, const bf16* __restrict__ Alo,
    const bf16* __restrict__ Bhi, const bf16* __restrict__ Blo,
    float* __restrict__ C, bf16* __restrict__ Ghi, bf16* __restrict__ Glo,
    const float* __restrict__ bias, const float* __restrict__ xres,
    int M, int N, int K, int mode) {
    extern __shared__ bf16 smem[];
    const int tid  = threadIdx.x;
    const int lane = tid & 31, wid = tid >> 5;
    const int bm = blockIdx.y, bn = blockIdx.x;
    const int warp_m = (wid & 1) * 64;
    const int warp_n = (wid >> 1) * 32;

    // ldmatrix lane-address components
    const int lq = lane & 7, lg = lane >> 3;
    const int aro = lq + (lg & 1) * 8;
    const int aco = (lg >> 1) * 8;
    const int bro = lq + (lg >> 1) * 8;
    const int bco = (lg & 1) * 8;

    const int r  = tid >> 2;
    const int kc = (tid & 3) * 8;
    const bf16* gAhi = Ahi + (size_t)(bm * 128 + r) * K + kc;
    const bf16* gAlo = Alo + (size_t)(bm * 128 + r) * K + kc;
    const bf16* gBhi = Bhi + (size_t)(bn * 128 + r) * K + kc;
    const bf16* gBlo = Blo + (size_t)(bn * 128 + r) * K + kc;
    const size_t roff = (size_t)64 * K;

    unsigned sbase = smem_u32(smem);
    unsigned sA0 = sbase + (r * ASTR + kc) * 2;
    unsigned sA1 = sbase + ((r + 64) * ASTR + kc) * 2;

    float d[4][4][4];
    #pragma unroll
    for (int i = 0; i < 4; i++)
        #pragma unroll
        for (int j = 0; j < 4; j++)
            #pragma unroll
            for (int e = 0; e < 4; e++) d[i][j][e] = 0.0f;

    const int ntiles = K / 32;

    {
        cp16(sA0,               gAhi);
        cp16(sA1,               gAhi + roff);
        cp16(sA0 + 5120 * 2,    gAlo);
        cp16(sA1 + 5120 * 2,    gAlo + roff);
        cp16(sA0 + 10240 * 2,   gBhi);
        cp16(sA1 + 10240 * 2,   gBhi + roff);
        cp16(sA0 + 15360 * 2,   gBlo);
        cp16(sA1 + 15360 * 2,   gBlo + roff);
        asm volatile("cp.async.commit_group;\n");
    }

    for (int kt = 0; kt < ntiles; kt++) {
        if (kt + 1 < ntiles) {
            int kk = (kt + 1) * 32;
            unsigned so = ((kt + 1) & 1) * (STAGE_HALVES * 2);
            cp16(sA0 + so,             gAhi + kk);
            cp16(sA1 + so,             gAhi + kk + roff);
            cp16(sA0 + so + 5120 * 2,  gAlo + kk);
            cp16(sA1 + so + 5120 * 2,  gAlo + kk + roff);
            cp16(sA0 + so + 10240 * 2, gBhi + kk);
            cp16(sA1 + so + 10240 * 2, gBhi + kk + roff);
            cp16(sA0 + so + 15360 * 2, gBlo + kk);
            cp16(sA1 + so + 15360 * 2, gBlo + kk + roff);
            asm volatile("cp.async.commit_group;\n");
            asm volatile("cp.async.wait_group 1;\n");
        } else {
            asm volatile("cp.async.wait_group 0;\n");
        }
        __syncthreads();

        const unsigned stb = sbase + (kt & 1) * (STAGE_HALVES * 2);
        #pragma unroll
        for (int ks = 0; ks < 2; ks++) {
            unsigned ahi[4][4], alo[4][4], bhi[4][2], blo[4][2];
            #pragma unroll
            for (int mt = 0; mt < 4; mt++) {
                unsigned ad = stb + ((warp_m + mt * 16 + aro) * ASTR + ks * 16 + aco) * 2;
                ldsm_x4(ahi[mt][0], ahi[mt][1], ahi[mt][2], ahi[mt][3], ad);
                ldsm_x4(alo[mt][0], alo[mt][1], alo[mt][2], alo[mt][3], ad + 5120 * 2);
            }
            #pragma unroll
            for (int np = 0; np < 2; np++) {
                unsigned bd = stb + 10240 * 2 +
                              ((warp_n + np * 16 + bro) * ASTR + ks * 16 + bco) * 2;
                ldsm_x4(bhi[2 * np][0], bhi[2 * np][1],
                        bhi[2 * np + 1][0], bhi[2 * np + 1][1], bd);
                ldsm_x4(blo[2 * np][0], blo[2 * np][1],
                        blo[2 * np + 1][0], blo[2 * np + 1][1], bd + 5120 * 2);
            }
            #pragma unroll
            for (int mt = 0; mt < 4; mt++)
                #pragma unroll
                for (int nt = 0; nt < 4; nt++) {
                    mma_bf16(d[mt][nt], ahi[mt][0], ahi[mt][1], ahi[mt][2], ahi[mt][3],
                             bhi[nt][0], bhi[nt][1]);
                    mma_bf16(d[mt][nt], ahi[mt][0], ahi[mt][1], ahi[mt][2], ahi[mt][3],
                             blo[nt][0], blo[nt][1]);
                    mma_bf16(d[mt][nt], alo[mt][0], alo[mt][1], alo[mt][2], alo[mt][3],
                             bhi[nt][0], bhi[nt][1]);
                }
        }
        __syncthreads();
    }

    // epilogue (modes)
    #pragma unroll
    for (int mt = 0; mt < 4; mt++) {
        int row = bm * 128 + warp_m + mt * 16 + (lane >> 2);
        #pragma unroll
        for (int nt = 0; nt < 4; nt++) {
            int col = bn * 128 + warp_n + nt * 8 + (lane & 3) * 2;
            if (mode == 0) {
                *(float2*)(C + (size_t)row * N + col) =
                    make_float2(d[mt][nt][0], d[mt][nt][1]);
                *(float2*)(C + (size_t)(row + 8) * N + col) =
                    make_float2(d[mt][nt][2], d[mt][nt][3]);
            } else if (mode == 2) {
                {
                    size_t o = (size_t)row * N + col;
                    *(float2*)(C + o) = make_float2(
                        d[mt][nt][0] + xres[o] + bias[col],
                        d[mt][nt][1] + xres[o + 1] + bias[col + 1]);
                }
                {
                    size_t o = (size_t)(row + 8) * N + col;
                    *(float2*)(C + o) = make_float2(
                        d[mt][nt][2] + xres[o] + bias[col],
                        d[mt][nt][3] + xres[o + 1] + bias[col + 1]);
                }
            } else {
                // swiglu: pair (col, col+1) = (a_n, gate_n), n = col/2
                int n = col >> 1;
                float ba = bias[n], bg = bias[DFF + n];
                float a0 = d[mt][nt][0] + ba, g0 = d[mt][nt][1] + bg;
                float a1 = d[mt][nt][2] + ba, g1 = d[mt][nt][3] + bg;
                float v0 = g0 * (1.0f / (1.0f + __expf(-g0))) * a0;
                float v1 = g1 * (1.0f / (1.0f + __expf(-g1))) * a1;
                bf16 hi, lo;
                split_bf(v0, hi, lo);
                Ghi[(size_t)row * DFF + n] = hi;       Glo[(size_t)row * DFF + n] = lo;
                split_bf(v1, hi, lo);
                Ghi[(size_t)(row + 8) * DFF + n] = hi; Glo[(size_t)(row + 8) * DFF + n] = lo;
            }
        }
    }
}

// ---------------- type-emb add + RoPE + head transpose -> bf16 hi/lo -------
// q scaled by 1/sqrt(HD) here. v handled by vtrans straight from qkv.
__global__ void rope_kernel(const float* __restrict__ qkv, const int* __restrict__ x_type,
                            const int* __restrict__ seq_order,
                            const float* __restrict__ type_emb,
                            bf16* __restrict__ qhi, bf16* __restrict__ qlo,
                            bf16* __restrict__ khi, bf16* __restrict__ klo) {
    int idx = blockIdx.x * 256 + threadIdx.x;
    int i = idx & 31;
    int t = (idx >> 5) & (Tt - 1);
    int h = (idx >> 15) & (Hh - 1);
    int b = idx >> 19;
    int row = b * Tt + t;
    int bh = b * Hh + h;
    int ty = x_type[row];

    const float* qrow = qkv + (size_t)row * D3;
    const float* te = type_emb + (size_t)ty * (2 * Dd);
    int cb = h * HD + 2 * i;

    float q0 = qrow[cb]           + te[cb];
    float q1 = qrow[cb + 1]       + te[cb + 1];
    float k0 = qrow[Dd + cb]      + te[Dd + cb];
    float k1 = qrow[Dd + cb + 1]  + te[Dd + cb + 1];

    if (i < 16) {
        float pos = (float)seq_order[row];
        float invf = __powf(10000.0f, -(float)i * (1.0f / 16.0f));
        float ang = pos * invf;
        float c, s;
        sincosf(ang, &s, &c);
        float rq0 = q0 * c - q1 * s;
        float rq1 = q1 * c + q0 * s;
        float rk0 = k0 * c - k1 * s;
        float rk1 = k1 * c + k0 * s;
        q0 = rq0; q1 = rq1; k0 = rk0; k1 = rk1;
    }
    q0 *= 0.125f; q1 *= 0.125f;
    size_t o = ((size_t)bh * Tt + t) * HD + 2 * i;
    bf16 hi, lo;
    split_bf(q0, hi, lo); qhi[o] = hi;     qlo[o] = lo;
    split_bf(q1, hi, lo); qhi[o + 1] = hi; qlo[o + 1] = lo;
    split_bf(k0, hi, lo); khi[o] = hi;     klo[o] = lo;
    split_bf(k1, hi, lo); khi[o + 1] = hi; klo[o + 1] = lo;
}

// ---------------- tensor-core flash attention ------------------------------
// grid (T/128, BH), 256 threads (8 warps x 16 q-rows). 64-key tiles.
// cp.async double-buffered K/V tiles in dynamic smem.
#define KSTR 72
#define AT_ARR   (64*KSTR)              // halves per array (4608)
#define AT_STAGE (4*AT_ARR)             // halves per stage (18432)

__global__ __launch_bounds__(256) void attn_mma_kernel(
    const bf16* __restrict__ qhi, const bf16* __restrict__ qlo,
    const bf16* __restrict__ khi, const bf16* __restrict__ klo,
    const bf16* __restrict__ vthi, const bf16* __restrict__ vtlo,
    float* __restrict__ out) {
    extern __shared__ bf16 asmem[];
    const unsigned sb = smem_u32(asmem);
    const int bh = blockIdx.y, qt = blockIdx.x;
    const int tid = threadIdx.x, lane = tid & 31, w = tid >> 5;
    const int g = lane >> 2, c = lane & 3;

    const int lq = lane & 7, lg = lane >> 3;
    const int bro = lq + (lg >> 1) * 8;
    const int bco = (lg & 1) * 8;

    // per-thread tile-load mapping
    const int lrr0 = tid >> 3;                 // rows 0..31 (it=0), +32 (it=1)
    const int lcc  = (tid & 7) * 8;

#define ALOAD(ktv, stv) do {                                                  \
    const size_t kg_ = ((size_t)bh * Tt + (ktv) * 64) * HD;                   \
    unsigned base_ = sb + (stv) * (AT_STAGE * 2);                             \
    _Pragma("unroll")                                                         \
    for (int it = 0; it < 2; it++) {                                          \
        int rr = lrr0 + it * 32;                                              \
        unsigned so = (rr * KSTR + lcc) * 2;                                  \
        cp16(base_ + so,                    khi + kg_ + rr * HD + lcc);       \
        cp16(base_ + AT_ARR * 2 + so,       klo + kg_ + rr * HD + lcc);       \
        size_t vg_ = ((size_t)bh * HD + rr) * Tt + (ktv) * 64 + lcc;          \
        cp16(base_ + 2 * AT_ARR * 2 + so,   vthi + vg_);                      \
        cp16(base_ + 3 * AT_ARR * 2 + so,   vtlo + vg_);                      \
    }                                                                         \
    asm volatile("cp.async.commit_group;\n");                                 \
} while (0)

    const int qrow0 = qt * 128 + w * 16 + g;
    unsigned qh[4][4], ql[4][4];

    ALOAD(0, 0);

    {
        const size_t base0 = ((size_t)bh * Tt + qrow0) * HD;
        const size_t base8 = base0 + 8 * HD;
        #pragma unroll
        for (int kk = 0; kk < 4; kk++) {
            int col = kk * 16 + 2 * c;
            qh[kk][0] = ld_u32(qhi + base0 + col);
            qh[kk][1] = ld_u32(qhi + base8 + col);
            qh[kk][2] = ld_u32(qhi + base0 + col + 8);
            qh[kk][3] = ld_u32(qhi + base8 + col + 8);
            ql[kk][0] = ld_u32(qlo + base0 + col);
            ql[kk][1] = ld_u32(qlo + base8 + col);
            ql[kk][2] = ld_u32(qlo + base0 + col + 8);
            ql[kk][3] = ld_u32(qlo + base8 + col + 8);
        }
    }

    float O[8][4];
    #pragma unroll
    for (int i = 0; i < 8; i++)
        #pragma unroll
        for (int j = 0; j < 4; j++) O[i][j] = 0.0f;
    float m0 = -1e30f, m1 = -1e30f, l0 = 0.0f, l1 = 0.0f;

    for (int kt = 0; kt < Tt / 64; kt++) {
        if (kt + 1 < Tt / 64) {
            ALOAD(kt + 1, (kt + 1) & 1);
            asm volatile("cp.async.wait_group 1;\n");
        } else {
            asm volatile("cp.async.wait_group 0;\n");
        }
        __syncthreads();

        const unsigned skh_b = sb + (kt & 1) * (AT_STAGE * 2);
        const unsigned skl_b = skh_b + AT_ARR * 2;
        const unsigned svh_b = skh_b + 2 * AT_ARR * 2;
        const unsigned svl_b = skh_b + 3 * AT_ARR * 2;

        // ---- S = Q K^T (3-pass), K frags via ldmatrix ----
        float S[8][4];
        #pragma unroll
        for (int i = 0; i < 8; i++)
            #pragma unroll
            for (int j = 0; j < 4; j++) S[i][j] = 0.0f;
        #pragma unroll
        for (int kk = 0; kk < 4; kk++) {
            #pragma unroll
            for (int np = 0; np < 4; np++) {
                unsigned off = ((np * 16 + bro) * KSTR + kk * 16 + bco) * 2;
                unsigned h0, h1, h2, h3, l0r, l1r, l2r, l3r;
                ldsm_x4(h0, h1, h2, h3, skh_b + off);
                ldsm_x4(l0r, l1r, l2r, l3r, skl_b + off);
                mma_bf16(S[2 * np],     qh[kk][0], qh[kk][1], qh[kk][2], qh[kk][3], h0, h1);
                mma_bf16(S[2 * np],     qh[kk][0], qh[kk][1], qh[kk][2], qh[kk][3], l0r, l1r);
                mma_bf16(S[2 * np],     ql[kk][0], ql[kk][1], ql[kk][2], ql[kk][3], h0, h1);
                mma_bf16(S[2 * np + 1], qh[kk][0], qh[kk][1], qh[kk][2], qh[kk][3], h2, h3);
                mma_bf16(S[2 * np + 1], qh[kk][0], qh[kk][1], qh[kk][2], qh[kk][3], l2r, l3r);
                mma_bf16(S[2 * np + 1], ql[kk][0], ql[kk][1], ql[kk][2], ql[kk][3], h2, h3);
            }
        }

        // ---- online softmax ----
        float tm0 = -1e30f, tm1 = -1e30f;
        #pragma unroll
        for (int nn = 0; nn < 8; nn++) {
            tm0 = fmaxf(tm0, fmaxf(S[nn][0], S[nn][1]));
            tm1 = fmaxf(tm1, fmaxf(S[nn][2], S[nn][3]));
        }
        tm0 = fmaxf(tm0, __shfl_xor_sync(0xffffffffu, tm0, 1));
        tm0 = fmaxf(tm0, __shfl_xor_sync(0xffffffffu, tm0, 2));
        tm1 = fmaxf(tm1, __shfl_xor_sync(0xffffffffu, tm1, 1));
        tm1 = fmaxf(tm1, __shfl_xor_sync(0xffffffffu, tm1, 2));
        float mn0 = fmaxf(m0, tm0), mn1 = fmaxf(m1, tm1);
        float cor0 = __expf(m0 - mn0), cor1 = __expf(m1 - mn1);
        m0 = mn0; m1 = mn1;

        float rs0 = 0.0f, rs1 = 0.0f;
        #pragma unroll
        for (int nn = 0; nn < 8; nn++) {
            S[nn][0] = __expf(S[nn][0] - mn0);
            S[nn][1] = __expf(S[nn][1] - mn0);
            S[nn][2] = __expf(S[nn][2] - mn1);
            S[nn][3] = __expf(S[nn][3] - mn1);
            rs0 += S[nn][0] + S[nn][1];
            rs1 += S[nn][2] + S[nn][3];
        }
        rs0 += __shfl_xor_sync(0xffffffffu, rs0, 1);
        rs0 += __shfl_xor_sync(0xffffffffu, rs0, 2);
        rs1 += __shfl_xor_sync(0xffffffffu, rs1, 1);
        rs1 += __shfl_xor_sync(0xffffffffu, rs1, 2);
        l0 = l0 * cor0 + rs0;
        l1 = l1 * cor1 + rs1;
        #pragma unroll
        for (int dd = 0; dd < 8; dd++) {
            O[dd][0] *= cor0; O[dd][1] *= cor0;
            O[dd][2] *= cor1; O[dd][3] *= cor1;
        }

        // ---- O += P V (3-pass); V via ldmatrix ----
        #pragma unroll
        for (int jj = 0; jj < 4; jj++) {
            float ph[8], pl[8];
            #pragma unroll
            for (int e = 0; e < 4; e++) {
                float v0 = S[2 * jj][e];
                float v1 = S[2 * jj + 1][e];
                float h0 = __bfloat162float(__float2bfloat16(v0));
                float h1 = __bfloat162float(__float2bfloat16(v1));
                ph[e]     = h0; ph[4 + e] = h1;
                pl[e]     = v0 - h0; pl[4 + e] = v1 - h1;
            }
            unsigned pah0 = pack_bf2(ph[0], ph[1]);
            unsigned pah1 = pack_bf2(ph[2], ph[3]);
            unsigned pah2 = pack_bf2(ph[4], ph[5]);
            unsigned pah3 = pack_bf2(ph[6], ph[7]);
            unsigned pal0 = pack_bf2(pl[0], pl[1]);
            unsigned pal1 = pack_bf2(pl[2], pl[3]);
            unsigned pal2 = pack_bf2(pl[4], pl[5]);
            unsigned pal3 = pack_bf2(pl[6], pl[7]);
            #pragma unroll
            for (int dp = 0; dp < 4; dp++) {
                unsigned off = ((dp * 16 + bro) * KSTR + jj * 16 + bco) * 2;
                unsigned v0r, v1r, v2r, v3r, w0r, w1r, w2r, w3r;
                ldsm_x4(v0r, v1r, v2r, v3r, svh_b + off);
                ldsm_x4(w0r, w1r, w2r, w3r, svl_b + off);
                mma_bf16(O[2 * dp],     pah0, pah1, pah2, pah3, v0r, v1r);
                mma_bf16(O[2 * dp],     pah0, pah1, pah2, pah3, w0r, w1r);
                mma_bf16(O[2 * dp],     pal0, pal1, pal2, pal3, v0r, v1r);
                mma_bf16(O[2 * dp + 1], pah0, pah1, pah2, pah3, v2r, v3r);
                mma_bf16(O[2 * dp + 1], pah0, pah1, pah2, pah3, w2r, w3r);
                mma_bf16(O[2 * dp + 1], pal0, pal1, pal2, pal3, v2r, v3r);
            }
        }
        __syncthreads();
    }

    float inv0 = 1.0f / l0, inv1 = 1.0f / l1;
    const int b = bh >> 4, h = bh & 15;
    const int trow = qt * 128 + w * 16 + g;
    #pragma unroll
    for (int dd = 0; dd < 8; dd++) {
        int col = h * HD + dd * 8 + 2 * c;
        *(float2*)(out + ((size_t)(b * Tt + trow)) * Dd + col) =
            make_float2(O[dd][0] * inv0, O[dd][1] * inv0);
        *(float2*)(out + ((size_t)(b * Tt + trow + 8)) * Dd + col) =
            make_float2(O[dd][2] * inv1, O[dd][3] * inv1);
    }
#undef ALOAD
}

// ---------------- launch ----------------------------------------------------
extern "C" void kernel_launch(void* const* d_in, const int* in_sizes, int n_in,
                              void* d_out, int out_size) {
    const int*   x_type    = (const int*)  d_in[0];
    const float* x_value   = (const float*)d_in[1];
    const int*   seq_order = (const int*)  d_in[2];
    const float* Wqkv      = (const float*)d_in[3];
    const float* type_emb  = (const float*)d_in[4];
    const float* ln1_w     = (const float*)d_in[5];
    const float* ln1_b     = (const float*)d_in[6];
    const float* ln2_w     = (const float*)d_in[7];
    const float* ln2_b     = (const float*)d_in[8];
    const float* fc1_w     = (const float*)d_in[9];
    const float* fc1_b     = (const float*)d_in[10];
    const float* fc2_w     = (const float*)d_in[11];
    const float* fc2_b     = (const float*)d_in[12];
    float* out = (float*)d_out;

    float *qkv, *attn, *x;
    bf16 *qhi, *qlo, *khi, *klo, *vthi, *vtlo;
    bf16 *h_hi, *h_lo, *h2_hi, *h2_lo, *gg_hi, *gg_lo;
    bf16 *wqkv_hi, *wqkv_lo, *w1_hi, *w1_lo, *w2_hi, *w2_lo;
    cudaGetSymbolAddress((void**)&qkv,     g_qkv);
    cudaGetSymbolAddress((void**)&attn,    g_attn);
    cudaGetSymbolAddress((void**)&x,       g_x);
    cudaGetSymbolAddress((void**)&qhi,     g_qhi);
    cudaGetSymbolAddress((void**)&qlo,     g_qlo);
    cudaGetSymbolAddress((void**)&khi,     g_khi);
    cudaGetSymbolAddress((void**)&klo,     g_klo);
    cudaGetSymbolAddress((void**)&vthi,    g_vthi);
    cudaGetSymbolAddress((void**)&vtlo,    g_vtlo);
    cudaGetSymbolAddress((void**)&h_hi,    g_h_hi);
    cudaGetSymbolAddress((void**)&h_lo,    g_h_lo);
    cudaGetSymbolAddress((void**)&h2_hi,   g_h2_hi);
    cudaGetSymbolAddress((void**)&h2_lo,   g_h2_lo);
    cudaGetSymbolAddress((void**)&gg_hi,   g_g_hi);
    cudaGetSymbolAddress((void**)&gg_lo,   g_g_lo);
    cudaGetSymbolAddress((void**)&wqkv_hi, g_wqkv_hi);
    cudaGetSymbolAddress((void**)&wqkv_lo, g_wqkv_lo);
    cudaGetSymbolAddress((void**)&w1_hi,   g_w1_hi);
    cudaGetSymbolAddress((void**)&w1_lo,   g_w1_lo);
    cudaGetSymbolAddress((void**)&w2_hi,   g_w2_hi);
    cudaGetSymbolAddress((void**)&w2_lo,   g_w2_lo);

    cudaFuncSetAttribute(gemm_mma_kernel,
                         cudaFuncAttributeMaxDynamicSharedMemorySize, 2 * STAGE_HALVES * 2);
    const int smem_bytes = 2 * STAGE_HALVES * 2;      // 81920
    cudaFuncSetAttribute(attn_mma_kernel,
                         cudaFuncAttributeMaxDynamicSharedMemorySize, 2 * AT_STAGE * 2);
    const int at_smem = 2 * AT_STAGE * 2;             // 73728

    // weight conversion (+transpose to [N][K]); fc1 rows interleaved a/gate
    conv_w_kernel<<<dim3(D3 / 32, Dd / 32),   dim3(32, 8)>>>(Wqkv,  wqkv_hi, wqkv_lo, Dd, D3, 0);
    conv_w_kernel<<<dim3(DFF2 / 32, Dd / 32), dim3(32, 8)>>>(fc1_w, w1_hi,   w1_lo,   Dd, DFF2, 1);
    conv_w_kernel<<<dim3(Dd / 32, DFF / 32),  dim3(32, 8)>>>(fc2_w, w2_hi,   w2_lo,   DFF, Dd, 0);

    // 1. LN1 -> bf16 hi/lo
    ln_kernel<<<NT, 256>>>(x_value, nullptr, ln1_w, ln1_b, nullptr, h_hi, h_lo);
    // 2. QKV GEMM
    gemm_mma_kernel<<<dim3(D3 / 128, NT / 128), 256, smem_bytes>>>(
        h_hi, h_lo, wqkv_hi, wqkv_lo, qkv, nullptr, nullptr, nullptr, nullptr,
        NT, D3, Dd, 0);
    // 3. type-emb + RoPE -> q/k bf16 hi/lo
    rope_kernel<<<(Bb * Hh * Tt * 32) / 256, 256>>>(
        qkv, x_type, seq_order, type_emb, qhi, qlo, khi, klo);
    // 3b. v transpose + split straight from qkv
    vtrans_kernel<<<dim3(Tt / 32, HD / 32, BH), dim3(32, 8)>>>(qkv, vthi, vtlo);
    // 4. tensor-core flash attention (cp.async double-buffered)
    attn_mma_kernel<<<dim3(Tt / 128, BH), 256, at_smem>>>(
        qhi, qlo, khi, klo, vthi, vtlo, attn);
    // 5. residual + LN2 (saves x = x_value + attn)
    ln_kernel<<<NT, 256>>>(x_value, attn, ln2_w, ln2_b, x, h2_hi, h2_lo);
    // 6. fc1 GEMM + fused bias/swiglu -> g hi/lo
    gemm_mma_kernel<<<dim3(DFF2 / 128, NT / 128), 256, smem_bytes>>>(
        h2_hi, h2_lo, w1_hi, w1_lo, nullptr, gg_hi, gg_lo, fc1_b, nullptr,
        NT, DFF2, Dd, 1);
    // 7. fc2 GEMM + fused bias/residual -> out
    gemm_mma_kernel<<<dim3(Dd / 128, NT / 128), 256, smem_bytes>>>(
        gg_hi, gg_lo, w2_hi, w2_lo, out, nullptr, nullptr, fc2_b, x,
        NT, Dd, DFF, 2);
}